// round 13
// baseline (speedup 1.0000x reference)
#include <cuda_runtime.h>
#include <cstdint>

#define EPSF 1e-6f
#define ONE_M_EPS (1.0f - 1e-6f)
#define NEG_LOG_EPS 13.815510557964274f      /* -log(1e-6)   */
#define NEG_LOG_1ME 1.0000005000002918e-06f  /* -log(1-1e-6) */
#define INV_TEMP 14.285714285714285f         /* 1/0.07       */

typedef unsigned long long ull;

// ---------------- device scratch ----------------
__device__ float d_qk[8u * 1024u * 1024u];     // 32 MB sim matrix (qk dot products)
__device__ float d_rsum[8192], d_rsq[8192], d_rse[8192];   // per (b,l), reduced over s
__device__ float d_csum[8192], d_csq[8192], d_cse[8192];   // per (b,s), reduced over l
__device__ unsigned d_rmaxu[8192], d_cmaxu[8192];          // order-preserving-key float max
__device__ float d_sharp1[8192], d_sharp2[8192];
__device__ float d_rlog[8192], d_clog[8192];   // log sum exp denominators
__device__ double d_acc[8][8];   // per-b: 0 poscnt,1 negcnt,2 geopos,3 geoneg,4 loss1,5 loss2,6 loss3
__device__ double d_cacc[2];     // contrastive: pos sum, neg sum

// ---------------- helpers ----------------
__device__ __forceinline__ float warpSum(float v) {
#pragma unroll
    for (int o = 16; o > 0; o >>= 1) v += __shfl_down_sync(0xffffffffu, v, o);
    return v;
}
__device__ __forceinline__ float warpMax(float v) {
#pragma unroll
    for (int o = 16; o > 0; o >>= 1) v = fmaxf(v, __shfl_down_sync(0xffffffffu, v, o));
    return v;
}
__device__ __forceinline__ unsigned fkey(float f) {
    unsigned b = __float_as_uint(f);
    return (b & 0x80000000u) ? ~b : (b | 0x80000000u);
}
__device__ __forceinline__ float funkey(unsigned u) {
    return __uint_as_float((u & 0x80000000u) ? (u ^ 0x80000000u) : ~u);
}
// packed 2-wide fp32 FMA (sm_100+): c = a*b + c elementwise, exact IEEE fp32
__device__ __forceinline__ void ffma2(ull& c, ull a, ull b) {
    asm("fma.rn.f32x2 %0, %1, %2, %0;" : "+l"(c) : "l"(a), "l"(b));
}
__device__ __forceinline__ float2 unpack2(ull v) {
    float2 r;
    asm("mov.b64 {%0, %1}, %2;" : "=f"(r.x), "=f"(r.y) : "l"(v));
    return r;
}

// ---------------- zero accumulators ----------------
__global__ void k_zero() {
    int i = blockIdx.x * 1024 + threadIdx.x;
    if (i < 8192) {
        d_rsum[i] = 0.f; d_rsq[i] = 0.f; d_rse[i] = 0.f; d_rmaxu[i] = 0u;
        d_csum[i] = 0.f; d_csq[i] = 0.f; d_cse[i] = 0.f; d_cmaxu[i] = 0u;
    }
    if (i < 64) ((double*)d_acc)[i] = 0.0;
    if (i < 2) d_cacc[i] = 0.0;
}

// ---------------- GEMM (FFMA2) + fused stats epilogue ----------------
// d_qk[b,l,s] = sum_c q[b,l,c]*k[b,s,c]; 64x64 tile, 256 threads, 4x4 micro.
// Packed fp32x2 FMA: A stored transposed+duplicated (a,a); B transposed so
// (b_n0,b_n1) pairs load as one LDS.128. Accumulation order identical to the
// scalar version -> bit-identical results. K chunked by 32 (smem 25.3KB).
__global__ __launch_bounds__(256) void k_gemm(const float* __restrict__ Q,
                                              const float* __restrict__ Kp) {
    __shared__ __align__(16) float AsD[32 * 130];  // [k][2m] duplicated pairs
    __shared__ __align__(16) float Bs[32 * 68];    // [k][n]
    int b = blockIdx.z;
    int l0 = blockIdx.y * 64;
    int s0 = blockIdx.x * 64;
    const float* Qb = Q + (size_t)b * 1024 * 128;
    const float* Kb = Kp + (size_t)b * 1024 * 128;
    int tid = threadIdx.x;
    int tx = tid & 15, ty = tid >> 4;
    int lm = tid >> 3;   // load row 0..31
    int lk = tid & 7;    // load k-quad 0..7

    ull accp[4][2];
#pragma unroll
    for (int i = 0; i < 4; i++) { accp[i][0] = 0ull; accp[i][1] = 0ull; }

#pragma unroll
    for (int kc = 0; kc < 4; kc++) {
        int kbase = kc * 32;
#pragma unroll
        for (int it = 0; it < 2; it++) {
            int m = lm + 32 * it;
            float4 va = *(const float4*)(Qb + (size_t)(l0 + m) * 128 + kbase + lk * 4);
            *(float2*)(AsD + (4 * lk + 0) * 130 + 2 * m) = make_float2(va.x, va.x);
            *(float2*)(AsD + (4 * lk + 1) * 130 + 2 * m) = make_float2(va.y, va.y);
            *(float2*)(AsD + (4 * lk + 2) * 130 + 2 * m) = make_float2(va.z, va.z);
            *(float2*)(AsD + (4 * lk + 3) * 130 + 2 * m) = make_float2(va.w, va.w);
            float4 vb = *(const float4*)(Kb + (size_t)(s0 + m) * 128 + kbase + lk * 4);
            Bs[(4 * lk + 0) * 68 + m] = vb.x;
            Bs[(4 * lk + 1) * 68 + m] = vb.y;
            Bs[(4 * lk + 2) * 68 + m] = vb.z;
            Bs[(4 * lk + 3) * 68 + m] = vb.w;
        }
        __syncthreads();
#pragma unroll
        for (int kk = 0; kk < 32; kk++) {
            ull a0 = *(const ull*)(AsD + kk * 130 + 8 * ty + 0);
            ull a1 = *(const ull*)(AsD + kk * 130 + 8 * ty + 2);
            ull a2 = *(const ull*)(AsD + kk * 130 + 8 * ty + 4);
            ull a3 = *(const ull*)(AsD + kk * 130 + 8 * ty + 6);
            ulonglong2 bq = *(const ulonglong2*)(Bs + kk * 68 + 4 * tx);
            ffma2(accp[0][0], a0, bq.x); ffma2(accp[0][1], a0, bq.y);
            ffma2(accp[1][0], a1, bq.x); ffma2(accp[1][1], a1, bq.y);
            ffma2(accp[2][0], a2, bq.x); ffma2(accp[2][1], a2, bq.y);
            ffma2(accp[3][0], a3, bq.x); ffma2(accp[3][1], a3, bq.y);
        }
        __syncthreads();
    }
    float acc[4][4];
#pragma unroll
    for (int i = 0; i < 4; i++) {
        float2 c01 = unpack2(accp[i][0]);
        float2 c23 = unpack2(accp[i][1]);
        acc[i][0] = c01.x; acc[i][1] = c01.y; acc[i][2] = c23.x; acc[i][3] = c23.y;
    }
#pragma unroll
    for (int i = 0; i < 4; i++) {
        float4 o = make_float4(acc[i][0], acc[i][1], acc[i][2], acc[i][3]);
        *(float4*)(d_qk + (size_t)(b * 1024 + l0 + 4 * ty + i) * 1024 + s0 + tx * 4) = o;
    }

    // ---- fused stats epilogue (unchanged) ----
    float rsum[4] = {0.f, 0.f, 0.f, 0.f}, rsq[4] = {0.f, 0.f, 0.f, 0.f};
    float rse[4] = {0.f, 0.f, 0.f, 0.f}, rmx[4] = {-1e30f, -1e30f, -1e30f, -1e30f};
    float csum[4] = {0.f, 0.f, 0.f, 0.f}, csq[4] = {0.f, 0.f, 0.f, 0.f};
    float cse[4] = {0.f, 0.f, 0.f, 0.f}, cmx[4] = {-1e30f, -1e30f, -1e30f, -1e30f};
#pragma unroll
    for (int i = 0; i < 4; i++) {
#pragma unroll
        for (int j = 0; j < 4; j++) {
            float x = acc[i][j];
            float e = expf(x * INV_TEMP);
            rsum[i] += x; rsq[i] = fmaf(x, x, rsq[i]); rse[i] += e; rmx[i] = fmaxf(rmx[i], x);
            csum[j] += x; csq[j] = fmaf(x, x, csq[j]); cse[j] += e; cmx[j] = fmaxf(cmx[j], x);
        }
    }
#pragma unroll
    for (int o = 1; o < 16; o <<= 1) {
#pragma unroll
        for (int i = 0; i < 4; i++) {
            rsum[i] += __shfl_xor_sync(0xffffffffu, rsum[i], o);
            rsq[i]  += __shfl_xor_sync(0xffffffffu, rsq[i], o);
            rse[i]  += __shfl_xor_sync(0xffffffffu, rse[i], o);
            rmx[i] = fmaxf(rmx[i], __shfl_xor_sync(0xffffffffu, rmx[i], o));
        }
    }
    if (tx == 0) {
#pragma unroll
        for (int i = 0; i < 4; i++) {
            int row = b * 1024 + l0 + 4 * ty + i;
            atomicAdd(&d_rsum[row], rsum[i]);
            atomicAdd(&d_rsq[row], rsq[i]);
            atomicAdd(&d_rse[row], rse[i]);
            atomicMax(&d_rmaxu[row], fkey(rmx[i]));
        }
    }
    float* SC = AsD;  // 4096 floats needed, 4160 available
#pragma unroll
    for (int j = 0; j < 4; j++) {
        int c = 4 * tx + j;
        SC[0 * 1024 + ty * 64 + c] = csum[j];
        SC[1 * 1024 + ty * 64 + c] = csq[j];
        SC[2 * 1024 + ty * 64 + c] = cse[j];
        SC[3 * 1024 + ty * 64 + c] = cmx[j];
    }
    __syncthreads();
    if (tid < 64) {
        float s0v = 0.f, s1v = 0.f, s2v = 0.f, s3v = -1e30f;
#pragma unroll
        for (int k = 0; k < 16; k++) {
            s0v += SC[0 * 1024 + k * 64 + tid];
            s1v += SC[1 * 1024 + k * 64 + tid];
            s2v += SC[2 * 1024 + k * 64 + tid];
            s3v = fmaxf(s3v, SC[3 * 1024 + k * 64 + tid]);
        }
        int col = b * 1024 + s0 + tid;
        atomicAdd(&d_csum[col], s0v);
        atomicAdd(&d_csq[col], s1v);
        atomicAdd(&d_cse[col], s2v);
        atomicMax(&d_cmaxu[col], fkey(s3v));
    }
}

// ---------------- sharpness softmax (merged row+col; 16 blocks x 1024) ----------------
__global__ __launch_bounds__(1024) void k_sharp(float* __restrict__ out) {
    __shared__ float sh[32];
    int which = blockIdx.x >> 3;   // 0 = row (l over s), 1 = col (s over l)
    int b = blockIdx.x & 7;
    const float* smp = which ? d_csum : d_rsum;
    const float* sqp = which ? d_csq : d_rsq;
    const float* sep = which ? d_cse : d_rse;
    const unsigned* mxp = which ? d_cmaxu : d_rmaxu;
    float* sharp = which ? d_sharp1 : d_sharp2;
    float* lse = which ? d_clog : d_rlog;
    int i = b * 1024 + threadIdx.x;
    float smv = smp[i];
    float mean = smv * (1.f / 1024.f);
    float var = (sqp[i] - smv * smv * (1.f / 1024.f)) * (1.f / 1023.f);
    float sv = (funkey(mxp[i]) - mean) / sqrtf(fmaxf(var, 1e-30f));
    lse[i] = logf(sep[i]);
    int lane = threadIdx.x & 31, w = threadIdx.x >> 5;
    float m = warpMax(sv);
    if (lane == 0) sh[w] = m;
    __syncthreads();
    if (w == 0) { float x = sh[lane]; x = warpMax(x); if (lane == 0) sh[0] = x; }
    __syncthreads();
    float M = sh[0];
    __syncthreads();
    float e = expf(sv - M);
    float s = warpSum(e);
    if (lane == 0) sh[w] = s;
    __syncthreads();
    if (w == 0) { float x = sh[lane]; x = warpSum(x); if (lane == 0) sh[0] = x; }
    __syncthreads();
    float S = sh[0];
    float o = e / S;
    sharp[i] = o;
    if (which) out[i] = o;   // sharpness output = sharp1
}

// ---------------- main masked accumulation over (b,l,s) ----------------
// One WARP per l-row (8 rows/block); deep independent load queue.
__global__ __launch_bounds__(256) void k_main(const int* __restrict__ label) {
    int b = blockIdx.y;
    int l0 = blockIdx.x * 8;
    int w = threadIdx.x >> 5;      // warp -> row l0 + w
    int lane = threadIdx.x & 31;
    int row = b * 1024 + l0 + w;
    const float4* qrow = (const float4*)(d_qk + (size_t)row * 1024);
    const int4* lrow = (const int4*)(label + (size_t)row * 1024);
    const float4* clog4 = (const float4*)(d_clog + b * 1024);
    const float4* sh14 = (const float4*)(d_sharp1 + b * 1024);
    float logrs = d_rlog[row];
    float sh2 = d_sharp2[row];
    const float C0 = -logf(1.0f - 1e-6f);     // -log(fl(1-1e-6)) reference form
    const float T_LO = -13.815510557964274f;  // log(1e-6)

    float poscnt = 0.f, negcnt = 0.f, gp = 0.f, gn = 0.f, L1 = 0.f, NLL = 0.f, L3 = 0.f;
#pragma unroll 4
    for (int k2 = 0; k2 < 8; k2++) {
        int idx = lane + 32 * k2;
        float4 xv = qrow[idx];
        int4 lv = lrow[idx];
        float4 cv = clog4[idx];
        float4 w1 = sh14[idx];
        float xs[4] = {xv.x, xv.y, xv.z, xv.w};
        int lb[4] = {lv.x, lv.y, lv.z, lv.w};
        float cs[4] = {cv.x, cv.y, cv.z, cv.w};
        float ws[4] = {w1.x, w1.y, w1.z, w1.w};
#pragma unroll
        for (int j = 0; j < 4; j++) {
            float x = xs[j];
            float t = fmaf(2.f * INV_TEMP, x, -cs[j] - logrs);
            float simc = fminf(fmaxf((1.f + x) * 0.5f, EPSF), ONE_M_EPS);
            if (lb[j] == 1) {
                poscnt += 1.f;
                gp += fminf(fmaxf(-t, NEG_LOG_1ME), NEG_LOG_EPS);  // -log(clip(conf))
                float nll = -__logf(simc);                          // simc ~ [0.25,0.75]
                L1 = fmaf(nll, ws[j], L1);
                NLL += nll;
            } else {
                negcnt += 1.f;
                if (t < T_LO) {
                    gn += C0;  // conf clipped at 1e-6: constant -log(fl(1-1e-6))
                } else {
                    float conf = fminf(__expf(t), ONE_M_EPS);
                    float y = 1.0f - conf;   // fp32-rounded subtraction (reference form)
                    float d = 1.0f - y;      // exact (Sterbenz): recovers rounded conf
                    if (d < 0.05f) {
                        gn += d * fmaf(d, fmaf(d, fmaf(d, 0.25f, 0.33333334f), 0.5f), 1.0f);
                    } else {
                        gn -= logf(y);       // rare (P ~ 1e-6): accurate path
                    }
                }
                float y3 = 1.0f - simc;      // ~ [0.25,0.75]
                L3 -= __logf(y3);
            }
        }
    }
    poscnt = warpSum(poscnt); negcnt = warpSum(negcnt);
    gp = warpSum(gp); gn = warpSum(gn);
    L1 = warpSum(L1); NLL = warpSum(NLL); L3 = warpSum(L3);
    __shared__ float sh[8][7];
    if (lane == 0) {
        sh[w][0] = poscnt; sh[w][1] = negcnt; sh[w][2] = gp; sh[w][3] = gn;
        sh[w][4] = L1; sh[w][5] = sh2 * NLL; sh[w][6] = L3;
    }
    __syncthreads();
    if (threadIdx.x < 7) {
        int k = threadIdx.x;
        float a = sh[0][k];
#pragma unroll
        for (int j = 1; j < 8; j++) a += sh[j][k];
        atomicAdd(&d_acc[b][k], (double)a);
    }
}

// ---------------- contrastive branch ----------------
__global__ __launch_bounds__(256) void k_cl(const float* __restrict__ q_cl,
                                            const float* __restrict__ cl_pos,
                                            const int* __restrict__ idx) {
    __shared__ float qn[8][128];
    __shared__ int sidx[8];
    int tid = threadIdx.x;
    if (tid < 8) sidx[tid] = idx[tid];
    __syncthreads();
    int w = tid >> 5, lane = tid & 31;
    {
        const float* qp = q_cl + ((size_t)w * 256 + sidx[w]) * 128;
        float4 v = ((const float4*)qp)[lane];
        float ss = v.x * v.x + v.y * v.y + v.z * v.z + v.w * v.w;
#pragma unroll
        for (int o = 16; o > 0; o >>= 1) ss += __shfl_xor_sync(0xffffffffu, ss, o);
        float inv = 1.f / fmaxf(sqrtf(ss), 1e-12f);
        ((float4*)&qn[w][0])[lane] = make_float4(v.x * inv, v.y * inv, v.z * inv, v.w * inv);
    }
    __syncthreads();
    int r = blockIdx.x * 256 + tid;  // all_k row 0..2047
    const float* kp;
    if (r < 8) {
        kp = cl_pos + ((size_t)r * 256 + sidx[r]) * 128;  // sel (positives)
    } else {
        int rr = r - 8;
        int n = rr / 255;
        int j = rr % 255 + 1;
        int jj = (j == sidx[n]) ? 0 : j;  // swapped
        kp = cl_pos + ((size_t)n * 256 + jj) * 128;
    }
    float dot[8] = {0.f, 0.f, 0.f, 0.f, 0.f, 0.f, 0.f, 0.f};
    float ksq = 0.f;
    const float4* kp4 = (const float4*)kp;
#pragma unroll 8
    for (int c = 0; c < 32; c++) {
        float4 kv = kp4[c];
        ksq = fmaf(kv.x, kv.x, fmaf(kv.y, kv.y, fmaf(kv.z, kv.z, fmaf(kv.w, kv.w, ksq))));
#pragma unroll
        for (int q = 0; q < 8; q++) {
            float4 qv = ((const float4*)qn[q])[c];
            dot[q] = fmaf(kv.x, qv.x, fmaf(kv.y, qv.y, fmaf(kv.z, qv.z, fmaf(kv.w, qv.w, dot[q]))));
        }
    }
    float kinv = 1.f / fmaxf(sqrtf(ksq), 1e-12f);
    float negsum = 0.f;
    if (r < 8) {
        float sim = fminf(fmaxf((1.f + dot[r] * kinv) * 0.5f, EPSF), ONE_M_EPS);
        atomicAdd(&d_cacc[0], (double)(-logf(sim)));
    } else {
#pragma unroll
        for (int q = 0; q < 8; q++) {
            float sim = fminf(fmaxf((1.f + dot[q] * kinv) * 0.5f, EPSF), ONE_M_EPS);
            float y = 1.0f - sim;       // fp32-rounded subtraction (reference form)
            negsum -= logf(y);
        }
    }
    __shared__ float sred[8];
    negsum = warpSum(negsum);
    if (lane == 0) sred[w] = negsum;
    __syncthreads();
    if (tid == 0) {
        float a = sred[0];
#pragma unroll
        for (int j = 1; j < 8; j++) a += sred[j];
        atomicAdd(&d_cacc[1], (double)a);
    }
}

// ---------------- finalize scalars + cl_pos_save ----------------
__global__ __launch_bounds__(1024) void k_final(const float* __restrict__ cl_pos,
                                                const int* __restrict__ idx,
                                                float* __restrict__ out) {
    int tid = threadIdx.x;
    int n = tid >> 7, c = tid & 127;
    out[8192 + tid] = cl_pos[((size_t)n * 256 + idx[n]) * 128 + c];
    if (tid == 0) {
        double gp = 0.0, gn = 0.0, ls = 0.0;
        for (int b = 0; b < 8; b++) {
            double pc = d_acc[b][0]; if (pc < 1.0) pc = 1.0;
            double nc = d_acc[b][1]; if (nc < 1.0) nc = 1.0;
            gp += d_acc[b][2] / pc;
            gn += d_acc[b][3] / nc;
            ls += 0.5 * (d_acc[b][4] + d_acc[b][5]) + d_acc[b][6] / nc;
        }
        gp *= 0.125; gn *= 0.125; ls *= 0.125;
        double loss_geo = gp + gn;
        double geo_comb = (0.5 * loss_geo + 0.5 * ls) * 0.5;  // W_SHARP, W_LOCAL
        double contrast = (d_cacc[0] * (1.0 / 8.0) + d_cacc[1] * (1.0 / 16320.0)) * 0.5;
        double lcl = contrast * 0.5;  // * (1 - W_LOCAL)
        out[9216] = (float)(geo_comb + lcl);  // total
        out[9217] = (float)gp;                // geo_pos_loss
        out[9218] = (float)gn;                // geo_neg_loss
        out[9219] = (float)ls;                // loss_sharp
        out[9220] = (float)lcl;               // loss_cl
    }
}

extern "C" void kernel_launch(void* const* d_in, const int* in_sizes, int n_in,
                              void* d_out, int out_size) {
    const float* q_geo   = (const float*)d_in[0];
    const float* q_cl    = (const float*)d_in[1];
    const float* geo_pos = (const float*)d_in[2];
    const float* cl_pos  = (const float*)d_in[3];
    const int*   label   = (const int*)d_in[4];
    const int*   idx     = (const int*)d_in[5];
    float* out = (float*)d_out;

    k_zero<<<8, 1024>>>();
    k_gemm<<<dim3(16, 16, 8), 256>>>(q_geo, geo_pos);
    k_sharp<<<16, 1024>>>(out);
    k_main<<<dim3(128, 8), 256>>>(label);
    k_cl<<<8, 256>>>(q_cl, cl_pos, idx);
    k_final<<<1, 1024>>>(cl_pos, idx, out);
}

// round 16
// speedup vs baseline: 1.2312x; 1.2312x over previous
#include <cuda_runtime.h>
#include <cstdint>

#define EPSF 1e-6f
#define ONE_M_EPS (1.0f - 1e-6f)
#define NEG_LOG_EPS 13.815510557964274f      /* -log(1e-6)   */
#define NEG_LOG_1ME 1.0000005000002918e-06f  /* -log(1-1e-6) */
#define INV_TEMP 14.285714285714285f         /* 1/0.07       */

// ---------------- device scratch ----------------
__device__ float d_qk[8u * 1024u * 1024u];     // 32 MB sim matrix (qk dot products)
__device__ float d_rsum[8192], d_rsq[8192], d_rse[8192];   // per (b,l), reduced over s
__device__ float d_csum[8192], d_csq[8192], d_cse[8192];   // per (b,s), reduced over l
__device__ unsigned d_rmaxu[8192], d_cmaxu[8192];          // order-preserving-key float max
__device__ float d_sharp1[8192], d_sharp2[8192];
__device__ float d_rlog[8192], d_clog[8192];   // log sum exp denominators
__device__ double d_acc[8][8];   // per-b: 0 poscnt,1 negcnt,2 geopos,3 geoneg,4 loss1,5 loss2,6 loss3
__device__ double d_cacc[2];     // contrastive: pos sum, neg sum

// ---------------- helpers ----------------
__device__ __forceinline__ float warpSum(float v) {
#pragma unroll
    for (int o = 16; o > 0; o >>= 1) v += __shfl_down_sync(0xffffffffu, v, o);
    return v;
}
__device__ __forceinline__ float warpMax(float v) {
#pragma unroll
    for (int o = 16; o > 0; o >>= 1) v = fmaxf(v, __shfl_down_sync(0xffffffffu, v, o));
    return v;
}
__device__ __forceinline__ unsigned fkey(float f) {
    unsigned b = __float_as_uint(f);
    return (b & 0x80000000u) ? ~b : (b | 0x80000000u);
}
__device__ __forceinline__ float funkey(unsigned u) {
    return __uint_as_float((u & 0x80000000u) ? (u ^ 0x80000000u) : ~u);
}

// ---------------- zero accumulators ----------------
__global__ void k_zero() {
    int i = blockIdx.x * 1024 + threadIdx.x;
    if (i < 8192) {
        d_rsum[i] = 0.f; d_rsq[i] = 0.f; d_rse[i] = 0.f; d_rmaxu[i] = 0u;
        d_csum[i] = 0.f; d_csq[i] = 0.f; d_cse[i] = 0.f; d_cmaxu[i] = 0u;
    }
    if (i < 64) ((double*)d_acc)[i] = 0.0;
    if (i < 2) d_cacc[i] = 0.0;
}

// ---------------- GEMM + fused stats epilogue ----------------
// d_qk[b,l,s] = sum_c q[b,l,c]*k[b,s,c]
// 128x64 tile, 256 threads, 8x4 micro-tile. Both A and B stored k-major
// (transposed) in smem: per k-step 2 broadcast LDS.128 (A) + 1 LDS.128 (B)
// + 32 FFMA -> issue ratio 35/32 vs the old 21/16. Accumulation per output
// is sequential k=0..127 -> bit-identical to the scalar 4x4 version.
__global__ __launch_bounds__(256) void k_gemm(const float* __restrict__ Q,
                                              const float* __restrict__ Kp) {
    __shared__ __align__(16) float As[32 * 132];  // [k][m] transposed, pad 132
    __shared__ __align__(16) float Bs[32 * 68];   // [k][n] transposed, pad 68
    int b = blockIdx.z;
    int l0 = blockIdx.y * 128;
    int s0 = blockIdx.x * 64;
    const float* Qb = Q + (size_t)b * 1024 * 128;
    const float* Kb = Kp + (size_t)b * 1024 * 128;
    int tid = threadIdx.x;
    int tx = tid & 15, ty = tid >> 4;   // cols 4*tx.., rows 8*ty..
    int lm = tid >> 3;                  // load row 0..31
    int lk = tid & 7;                   // load k-quad 0..7

    float acc[8][4];
#pragma unroll
    for (int i = 0; i < 8; i++)
#pragma unroll
        for (int j = 0; j < 4; j++) acc[i][j] = 0.f;

    for (int kc = 0; kc < 4; kc++) {
        int kbase = kc * 32;
        // A chunk: 128 rows x 32 k, stored transposed As[k][m]
#pragma unroll
        for (int it = 0; it < 4; it++) {
            int m = lm + 32 * it;
            float4 v = *(const float4*)(Qb + (size_t)(l0 + m) * 128 + kbase + lk * 4);
            As[(4 * lk + 0) * 132 + m] = v.x;
            As[(4 * lk + 1) * 132 + m] = v.y;
            As[(4 * lk + 2) * 132 + m] = v.z;
            As[(4 * lk + 3) * 132 + m] = v.w;
        }
        // B chunk: 64 rows x 32 k, stored transposed Bs[k][n]
#pragma unroll
        for (int it = 0; it < 2; it++) {
            int n = lm + 32 * it;
            float4 v = *(const float4*)(Kb + (size_t)(s0 + n) * 128 + kbase + lk * 4);
            Bs[(4 * lk + 0) * 68 + n] = v.x;
            Bs[(4 * lk + 1) * 68 + n] = v.y;
            Bs[(4 * lk + 2) * 68 + n] = v.z;
            Bs[(4 * lk + 3) * 68 + n] = v.w;
        }
        __syncthreads();
#pragma unroll 16
        for (int kk = 0; kk < 32; kk++) {
            float4 a0 = *(const float4*)(As + kk * 132 + 8 * ty);
            float4 a1 = *(const float4*)(As + kk * 132 + 8 * ty + 4);
            float4 bv = *(const float4*)(Bs + kk * 68 + 4 * tx);
            float a[8] = {a0.x, a0.y, a0.z, a0.w, a1.x, a1.y, a1.z, a1.w};
#pragma unroll
            for (int i = 0; i < 8; i++) {
                acc[i][0] = fmaf(a[i], bv.x, acc[i][0]);
                acc[i][1] = fmaf(a[i], bv.y, acc[i][1]);
                acc[i][2] = fmaf(a[i], bv.z, acc[i][2]);
                acc[i][3] = fmaf(a[i], bv.w, acc[i][3]);
            }
        }
        __syncthreads();
    }
    // store tile
#pragma unroll
    for (int i = 0; i < 8; i++) {
        float4 o = make_float4(acc[i][0], acc[i][1], acc[i][2], acc[i][3]);
        *(float4*)(d_qk + (size_t)(b * 1024 + l0 + 8 * ty + i) * 1024 + s0 + tx * 4) = o;
    }

    // ---- fused stats epilogue ----
    float rsum[8], rsq[8], rse[8], rmx[8];
#pragma unroll
    for (int i = 0; i < 8; i++) { rsum[i] = 0.f; rsq[i] = 0.f; rse[i] = 0.f; rmx[i] = -1e30f; }
    float csum[4] = {0.f, 0.f, 0.f, 0.f}, csq[4] = {0.f, 0.f, 0.f, 0.f};
    float cse[4] = {0.f, 0.f, 0.f, 0.f}, cmx[4] = {-1e30f, -1e30f, -1e30f, -1e30f};
#pragma unroll
    for (int i = 0; i < 8; i++) {
#pragma unroll
        for (int j = 0; j < 4; j++) {
            float x = acc[i][j];
            float e = expf(x * INV_TEMP);
            rsum[i] += x; rsq[i] = fmaf(x, x, rsq[i]); rse[i] += e; rmx[i] = fmaxf(rmx[i], x);
            csum[j] += x; csq[j] = fmaf(x, x, csq[j]); cse[j] += e; cmx[j] = fmaxf(cmx[j], x);
        }
    }
    // row partials: reduce across the 16-lane tx group
#pragma unroll
    for (int o = 1; o < 16; o <<= 1) {
#pragma unroll
        for (int i = 0; i < 8; i++) {
            rsum[i] += __shfl_xor_sync(0xffffffffu, rsum[i], o);
            rsq[i]  += __shfl_xor_sync(0xffffffffu, rsq[i], o);
            rse[i]  += __shfl_xor_sync(0xffffffffu, rse[i], o);
            rmx[i] = fmaxf(rmx[i], __shfl_xor_sync(0xffffffffu, rmx[i], o));
        }
    }
    if (tx == 0) {
#pragma unroll
        for (int i = 0; i < 8; i++) {
            int row = b * 1024 + l0 + 8 * ty + i;
            atomicAdd(&d_rsum[row], rsum[i]);
            atomicAdd(&d_rsq[row], rsq[i]);
            atomicAdd(&d_rse[row], rse[i]);
            atomicMax(&d_rmaxu[row], fkey(rmx[i]));
        }
    }
    // col partials: smem reduce across ty (layout [stat][ty][col])
    float* SC = As;  // needs 4096 floats; As has 4224
#pragma unroll
    for (int j = 0; j < 4; j++) {
        int c = 4 * tx + j;
        SC[0 * 1024 + ty * 64 + c] = csum[j];
        SC[1 * 1024 + ty * 64 + c] = csq[j];
        SC[2 * 1024 + ty * 64 + c] = cse[j];
        SC[3 * 1024 + ty * 64 + c] = cmx[j];
    }
    __syncthreads();
    if (tid < 64) {
        float s0v = 0.f, s1v = 0.f, s2v = 0.f, s3v = -1e30f;
#pragma unroll
        for (int k = 0; k < 16; k++) {
            s0v += SC[0 * 1024 + k * 64 + tid];
            s1v += SC[1 * 1024 + k * 64 + tid];
            s2v += SC[2 * 1024 + k * 64 + tid];
            s3v = fmaxf(s3v, SC[3 * 1024 + k * 64 + tid]);
        }
        int col = b * 1024 + s0 + tid;
        atomicAdd(&d_csum[col], s0v);
        atomicAdd(&d_csq[col], s1v);
        atomicAdd(&d_cse[col], s2v);
        atomicMax(&d_cmaxu[col], fkey(s3v));
    }
}

// ---------------- sharpness softmax (merged row+col; 16 blocks x 1024) ----------------
__global__ __launch_bounds__(1024) void k_sharp(float* __restrict__ out) {
    __shared__ float sh[32];
    int which = blockIdx.x >> 3;   // 0 = row (l over s), 1 = col (s over l)
    int b = blockIdx.x & 7;
    const float* smp = which ? d_csum : d_rsum;
    const float* sqp = which ? d_csq : d_rsq;
    const float* sep = which ? d_cse : d_rse;
    const unsigned* mxp = which ? d_cmaxu : d_rmaxu;
    float* sharp = which ? d_sharp1 : d_sharp2;
    float* lse = which ? d_clog : d_rlog;
    int i = b * 1024 + threadIdx.x;
    float smv = smp[i];
    float mean = smv * (1.f / 1024.f);
    float var = (sqp[i] - smv * smv * (1.f / 1024.f)) * (1.f / 1023.f);
    float sv = (funkey(mxp[i]) - mean) / sqrtf(fmaxf(var, 1e-30f));
    lse[i] = logf(sep[i]);
    int lane = threadIdx.x & 31, w = threadIdx.x >> 5;
    float m = warpMax(sv);
    if (lane == 0) sh[w] = m;
    __syncthreads();
    if (w == 0) { float x = sh[lane]; x = warpMax(x); if (lane == 0) sh[0] = x; }
    __syncthreads();
    float M = sh[0];
    __syncthreads();
    float e = expf(sv - M);
    float s = warpSum(e);
    if (lane == 0) sh[w] = s;
    __syncthreads();
    if (w == 0) { float x = sh[lane]; x = warpSum(x); if (lane == 0) sh[0] = x; }
    __syncthreads();
    float S = sh[0];
    float o = e / S;
    sharp[i] = o;
    if (which) out[i] = o;   // sharpness output = sharp1
}

// ---------------- main masked accumulation over (b,l,s) ----------------
// One WARP per l-row (8 rows/block); deep independent load queue.
__global__ __launch_bounds__(256) void k_main(const int* __restrict__ label) {
    int b = blockIdx.y;
    int l0 = blockIdx.x * 8;
    int w = threadIdx.x >> 5;      // warp -> row l0 + w
    int lane = threadIdx.x & 31;
    int row = b * 1024 + l0 + w;
    const float4* qrow = (const float4*)(d_qk + (size_t)row * 1024);
    const int4* lrow = (const int4*)(label + (size_t)row * 1024);
    const float4* clog4 = (const float4*)(d_clog + b * 1024);
    const float4* sh14 = (const float4*)(d_sharp1 + b * 1024);
    float logrs = d_rlog[row];
    float sh2 = d_sharp2[row];
    const float C0 = -logf(1.0f - 1e-6f);     // -log(fl(1-1e-6)) reference form
    const float T_LO = -13.815510557964274f;  // log(1e-6)

    float poscnt = 0.f, negcnt = 0.f, gp = 0.f, gn = 0.f, L1 = 0.f, NLL = 0.f, L3 = 0.f;
#pragma unroll 4
    for (int k2 = 0; k2 < 8; k2++) {
        int idx = lane + 32 * k2;
        float4 xv = qrow[idx];
        int4 lv = lrow[idx];
        float4 cv = clog4[idx];
        float4 w1 = sh14[idx];
        float xs[4] = {xv.x, xv.y, xv.z, xv.w};
        int lb[4] = {lv.x, lv.y, lv.z, lv.w};
        float cs[4] = {cv.x, cv.y, cv.z, cv.w};
        float ws[4] = {w1.x, w1.y, w1.z, w1.w};
#pragma unroll
        for (int j = 0; j < 4; j++) {
            float x = xs[j];
            float t = fmaf(2.f * INV_TEMP, x, -cs[j] - logrs);
            float simc = fminf(fmaxf((1.f + x) * 0.5f, EPSF), ONE_M_EPS);
            if (lb[j] == 1) {
                poscnt += 1.f;
                gp += fminf(fmaxf(-t, NEG_LOG_1ME), NEG_LOG_EPS);  // -log(clip(conf))
                float nll = -__logf(simc);                          // simc ~ [0.25,0.75]
                L1 = fmaf(nll, ws[j], L1);
                NLL += nll;
            } else {
                negcnt += 1.f;
                if (t < T_LO) {
                    gn += C0;  // conf clipped at 1e-6: constant -log(fl(1-1e-6))
                } else {
                    float conf = fminf(__expf(t), ONE_M_EPS);
                    float y = 1.0f - conf;   // fp32-rounded subtraction (reference form)
                    float d = 1.0f - y;      // exact (Sterbenz): recovers rounded conf
                    if (d < 0.05f) {
                        gn += d * fmaf(d, fmaf(d, fmaf(d, 0.25f, 0.33333334f), 0.5f), 1.0f);
                    } else {
                        gn -= logf(y);       // rare (P ~ 1e-6): accurate path
                    }
                }
                float y3 = 1.0f - simc;      // ~ [0.25,0.75]
                L3 -= __logf(y3);
            }
        }
    }
    poscnt = warpSum(poscnt); negcnt = warpSum(negcnt);
    gp = warpSum(gp); gn = warpSum(gn);
    L1 = warpSum(L1); NLL = warpSum(NLL); L3 = warpSum(L3);
    __shared__ float sh[8][7];
    if (lane == 0) {
        sh[w][0] = poscnt; sh[w][1] = negcnt; sh[w][2] = gp; sh[w][3] = gn;
        sh[w][4] = L1; sh[w][5] = sh2 * NLL; sh[w][6] = L3;
    }
    __syncthreads();
    if (threadIdx.x < 7) {
        int k = threadIdx.x;
        float a = sh[0][k];
#pragma unroll
        for (int j = 1; j < 8; j++) a += sh[j][k];
        atomicAdd(&d_acc[b][k], (double)a);
    }
}

// ---------------- contrastive branch ----------------
__global__ __launch_bounds__(256) void k_cl(const float* __restrict__ q_cl,
                                            const float* __restrict__ cl_pos,
                                            const int* __restrict__ idx) {
    __shared__ float qn[8][128];
    __shared__ int sidx[8];
    int tid = threadIdx.x;
    if (tid < 8) sidx[tid] = idx[tid];
    __syncthreads();
    int w = tid >> 5, lane = tid & 31;
    {
        const float* qp = q_cl + ((size_t)w * 256 + sidx[w]) * 128;
        float4 v = ((const float4*)qp)[lane];
        float ss = v.x * v.x + v.y * v.y + v.z * v.z + v.w * v.w;
#pragma unroll
        for (int o = 16; o > 0; o >>= 1) ss += __shfl_xor_sync(0xffffffffu, ss, o);
        float inv = 1.f / fmaxf(sqrtf(ss), 1e-12f);
        ((float4*)&qn[w][0])[lane] = make_float4(v.x * inv, v.y * inv, v.z * inv, v.w * inv);
    }
    __syncthreads();
    int r = blockIdx.x * 256 + tid;  // all_k row 0..2047
    const float* kp;
    if (r < 8) {
        kp = cl_pos + ((size_t)r * 256 + sidx[r]) * 128;  // sel (positives)
    } else {
        int rr = r - 8;
        int n = rr / 255;
        int j = rr % 255 + 1;
        int jj = (j == sidx[n]) ? 0 : j;  // swapped
        kp = cl_pos + ((size_t)n * 256 + jj) * 128;
    }
    float dot[8] = {0.f, 0.f, 0.f, 0.f, 0.f, 0.f, 0.f, 0.f};
    float ksq = 0.f;
    const float4* kp4 = (const float4*)kp;
#pragma unroll 8
    for (int c = 0; c < 32; c++) {
        float4 kv = kp4[c];
        ksq = fmaf(kv.x, kv.x, fmaf(kv.y, kv.y, fmaf(kv.z, kv.z, fmaf(kv.w, kv.w, ksq))));
#pragma unroll
        for (int q = 0; q < 8; q++) {
            float4 qv = ((const float4*)qn[q])[c];
            dot[q] = fmaf(kv.x, qv.x, fmaf(kv.y, qv.y, fmaf(kv.z, qv.z, fmaf(kv.w, qv.w, dot[q]))));
        }
    }
    float kinv = 1.f / fmaxf(sqrtf(ksq), 1e-12f);
    float negsum = 0.f;
    if (r < 8) {
        float sim = fminf(fmaxf((1.f + dot[r] * kinv) * 0.5f, EPSF), ONE_M_EPS);
        atomicAdd(&d_cacc[0], (double)(-logf(sim)));
    } else {
#pragma unroll
        for (int q = 0; q < 8; q++) {
            float sim = fminf(fmaxf((1.f + dot[q] * kinv) * 0.5f, EPSF), ONE_M_EPS);
            float y = 1.0f - sim;       // fp32-rounded subtraction (reference form)
            negsum -= logf(y);
        }
    }
    __shared__ float sred[8];
    negsum = warpSum(negsum);
    if (lane == 0) sred[w] = negsum;
    __syncthreads();
    if (tid == 0) {
        float a = sred[0];
#pragma unroll
        for (int j = 1; j < 8; j++) a += sred[j];
        atomicAdd(&d_cacc[1], (double)a);
    }
}

// ---------------- finalize scalars + cl_pos_save ----------------
__global__ __launch_bounds__(1024) void k_final(const float* __restrict__ cl_pos,
                                                const int* __restrict__ idx,
                                                float* __restrict__ out) {
    int tid = threadIdx.x;
    int n = tid >> 7, c = tid & 127;
    out[8192 + tid] = cl_pos[((size_t)n * 256 + idx[n]) * 128 + c];
    if (tid == 0) {
        double gp = 0.0, gn = 0.0, ls = 0.0;
        for (int b = 0; b < 8; b++) {
            double pc = d_acc[b][0]; if (pc < 1.0) pc = 1.0;
            double nc = d_acc[b][1]; if (nc < 1.0) nc = 1.0;
            gp += d_acc[b][2] / pc;
            gn += d_acc[b][3] / nc;
            ls += 0.5 * (d_acc[b][4] + d_acc[b][5]) + d_acc[b][6] / nc;
        }
        gp *= 0.125; gn *= 0.125; ls *= 0.125;
        double loss_geo = gp + gn;
        double geo_comb = (0.5 * loss_geo + 0.5 * ls) * 0.5;  // W_SHARP, W_LOCAL
        double contrast = (d_cacc[0] * (1.0 / 8.0) + d_cacc[1] * (1.0 / 16320.0)) * 0.5;
        double lcl = contrast * 0.5;  // * (1 - W_LOCAL)
        out[9216] = (float)(geo_comb + lcl);  // total
        out[9217] = (float)gp;                // geo_pos_loss
        out[9218] = (float)gn;                // geo_neg_loss
        out[9219] = (float)ls;                // loss_sharp
        out[9220] = (float)lcl;               // loss_cl
    }
}

extern "C" void kernel_launch(void* const* d_in, const int* in_sizes, int n_in,
                              void* d_out, int out_size) {
    const float* q_geo   = (const float*)d_in[0];
    const float* q_cl    = (const float*)d_in[1];
    const float* geo_pos = (const float*)d_in[2];
    const float* cl_pos  = (const float*)d_in[3];
    const int*   label   = (const int*)d_in[4];
    const int*   idx     = (const int*)d_in[5];
    float* out = (float*)d_out;

    k_zero<<<8, 1024>>>();
    k_gemm<<<dim3(16, 8, 8), 256>>>(q_geo, geo_pos);
    k_sharp<<<16, 1024>>>(out);
    k_main<<<dim3(128, 8), 256>>>(label);
    k_cl<<<8, 256>>>(q_cl, cl_pos, idx);
    k_final<<<1, 1024>>>(cl_pos, idx, out);
}